// round 17
// baseline (speedup 1.0000x reference)
#include <cuda_runtime.h>
#include <cuda_fp16.h>
#include <cstdint>
#include <cstddef>

typedef unsigned int u32;

#define NEG_INFF (-9.0e15f)
#define BN_EPS 1e-5f

// ---------------- smem layout (bytes), 68-token CTA ----------------
// AH: [80 rows][264 k] fp16, stride 528 B (rows 68..79 padding for m-tile 4)
// AL: [80 rows][136 k] fp16, stride 272 B (x residual only, c 0..127)
#define AH_B   0u
#define AL_B   42240u          // 80*528
#define QS_B   64000u          // qs[68][36] f32 = 9792 ; ALSO qkv B-stage (26112) / conv W (33792 spans into mask)
#define KS_B   73792u
#define VS_B   83584u
#define MB_B   93376u          // mask 4*289 f32 = 4624
#define BNS_B  98000u
#define BNB_B  99024u
#define SMEM_BYTES 100048u

// ---------------- pre-packed fp16 weight images ----------------
// g_Bqkv[g][n*136+c]: n = third*32+nl (q:0-31, k:32-63, v:64-95), k-stride 136 halves (272 B rows)
__device__ __align__(16) __half g_Bqkv[4][96 * 136];
// g_Bconv[cb][n*264+c]: 4 chunks of 64 outputs, k-stride 264 halves (528 B rows), K=256
__device__ __align__(16) __half g_Bconv[4][64 * 264];

__global__ void prep_kernel(const float* __restrict__ Wq, const float* __restrict__ Wk,
                            const float* __restrict__ Wv, const float* __restrict__ cw) {
    int i = blockIdx.x * blockDim.x + threadIdx.x;
    if (i < 4 * 96 * 128) {
        int g = i / 12288; int r = i - g * 12288;
        int n = r >> 7, c = r & 127;
        int third = n >> 5, nl = n & 31;
        int h = g * 4 + (nl >> 3), e = nl & 7;
        const float* W = (third == 0) ? Wq : (third == 1 ? Wk : Wv);
        float w = W[h * 1024 + c * 8 + e];        // W[h][c][e] (16,128,8)
        g_Bqkv[g][n * 136 + c] = __float2half_rn(w);
    } else {
        int j = i - 4 * 96 * 128;
        if (j < 256 * 256) {
            int o = j >> 8, c = j & 255;
            int cb = o >> 6, n = o & 63;
            g_Bconv[cb][n * 264 + c] = __float2half_rn(cw[o * 256 + c]);
        }
    }
}

// ---------------- warp mma helpers ----------------
__device__ __forceinline__ u32 smem_u32(const void* p) {
    u32 a;
    asm("{ .reg .u64 t; cvta.to.shared.u64 t, %1; cvt.u32.u64 %0, t; }" : "=r"(a) : "l"(p));
    return a;
}
__device__ __forceinline__ void ldsm4(u32* r, u32 a) {
    asm volatile("ldmatrix.sync.aligned.m8n8.x4.shared.b16 {%0,%1,%2,%3}, [%4];"
                 : "=r"(r[0]), "=r"(r[1]), "=r"(r[2]), "=r"(r[3]) : "r"(a));
}
__device__ __forceinline__ void ldsm2(u32* r, u32 a) {
    asm volatile("ldmatrix.sync.aligned.m8n8.x2.shared.b16 {%0,%1}, [%2];"
                 : "=r"(r[0]), "=r"(r[1]) : "r"(a));
}
__device__ __forceinline__ void mma16816(float* c, const u32* a, const u32* b) {
    asm volatile(
        "mma.sync.aligned.m16n8k16.row.col.f32.f16.f16.f32 "
        "{%0,%1,%2,%3}, {%4,%5,%6,%7}, {%8,%9}, {%0,%1,%2,%3};"
        : "+f"(c[0]), "+f"(c[1]), "+f"(c[2]), "+f"(c[3])
        : "r"(a[0]), "r"(a[1]), "r"(a[2]), "r"(a[3]), "r"(b[0]), "r"(b[1]));
}
// split two floats into fp16 hi and fp16 residual (packed as half2 words)
__device__ __forceinline__ void split2h(float a, float b, u32& hu, u32& lu) {
    __half ha = __float2half_rn(a), hb = __float2half_rn(b);
    float ra = a - __half2float(ha), rb = b - __half2float(hb);
    __half la = __float2half_rn(ra), lb = __float2half_rn(rb);
    hu = (u32)__half_as_ushort(ha) | ((u32)__half_as_ushort(hb) << 16);
    lu = (u32)__half_as_ushort(la) | ((u32)__half_as_ushort(lb) << 16);
}
__device__ __forceinline__ void pack2h(float a, float b, u32& hu) {
    __half ha = __float2half_rn(a), hb = __float2half_rn(b);
    hu = (u32)__half_as_ushort(ha) | ((u32)__half_as_ushort(hb) << 16);
}
__device__ __forceinline__ void cpasync16(u32 dst, const void* src) {
    unsigned long long g;
    asm("cvta.to.global.u64 %0, %1;" : "=l"(g) : "l"(src));
    asm volatile("cp.async.cg.shared.global [%0], [%1], 16;" :: "r"(dst), "l"(g) : "memory");
}

extern __shared__ __align__(16) unsigned char sp[];

__global__ void __launch_bounds__(256, 2)
gab_kernel(const float* __restrict__ x, const float* __restrict__ adj,
           const float* __restrict__ adj2,
           const float* __restrict__ bng, const float* __restrict__ bnbv,
           const float* __restrict__ bnm, const float* __restrict__ bnv,
           float* __restrict__ out) {
    const u32 sb = smem_u32(sp);
    const int b  = blockIdx.x >> 7;        // 0..31
    const int tb = blockIdx.x & 127;       // 0..127
    const int t0 = tb * 4;
    const int tid  = threadIdx.x;
    const int lane = tid & 31;
    const int wid  = tid >> 5;             // 0..7

    // ---- Phase A: load X (68 tokens), fp16-split into AH (c 0..127) / AL (x residual) ----
    {
        const float* xb = x + (size_t)b * 128 * 8704 + (size_t)t0 * 17;
        for (int d4 = wid; d4 < 32; d4 += 8) {
            const float* s0 = xb + (size_t)(d4 * 4 + 0) * 8704;
            const float* s1 = xb + (size_t)(d4 * 4 + 1) * 8704;
            const float* s2 = xb + (size_t)(d4 * 4 + 2) * 8704;
            const float* s3 = xb + (size_t)(d4 * 4 + 3) * 8704;
            for (int tok = lane; tok < 68; tok += 32) {
                float v0 = s0[tok], v1 = s1[tok], v2 = s2[tok], v3 = s3[tok];
                u32 h01, l01, h23, l23;
                split2h(v0, v1, h01, l01);
                split2h(v2, v3, h23, l23);
                *(uint2*)(sp + AH_B + (u32)tok * 528u + (u32)d4 * 8u) = make_uint2(h01, h23);
                *(uint2*)(sp + AL_B + (u32)tok * 272u + (u32)d4 * 8u) = make_uint2(l01, l23);
            }
        }
    }
    // ---- BN fold ----
    {
        float sc = bng[tid] * rsqrtf(bnv[tid] + BN_EPS);
        ((float*)(sp + BNS_B))[tid] = sc;
        ((float*)(sp + BNB_B))[tid] = bnbv[tid] - bnm[tid] * sc;
    }

    const float inv_s = 0.3535533905932738f;   // 1/sqrt(8)
    float* qsf = (float*)(sp + QS_B);
    float* ksf = (float*)(sp + KS_B);
    float* vsf = (float*)(sp + VS_B);
    float* mbf = (float*)(sp + MB_B);
    const int row_lo0 = (lane >> 2);
    const int col0 = (lane & 3) * 2;

    // ---- Phase B: 4 head-groups; per group: ONE merged qkv stage, then attention ----
    for (int g = 0; g < 4; ++g) {
        __syncthreads();   // prev-group attention / Phase A complete; qs region dead
        // stage merged B (96 cols x 128 k = 26112 B) into QS region via cp.async
        {
            const char* src = (const char*)&g_Bqkv[g][0];
            for (int j = tid; j < 1632; j += 256)
                cpasync16(sb + QS_B + (u32)j * 16u, src + (size_t)j * 16);
            asm volatile("cp.async.commit_group;" ::: "memory");
            asm volatile("cp.async.wait_group 0;" ::: "memory");
        }
        // mask bias for this group
        for (int idx = tid; idx < 4 * 289; idx += 256) {
            int hl = idx / 289, r = idx - hl * 289;
            int n = r / 17, m = r - n * 17;
            int hh = g * 4 + hl;
            float a = 0.5f * (adj[n * 17 + m] + adj[m * 17 + n])
                    + 0.5f * (adj2[hh * 289 + n * 17 + m] + adj2[hh * 289 + m * 17 + n]);
            mbf[idx] = (a > 0.0f) ? 0.0f : NEG_INFF;
        }
        __syncthreads();   // B + mask visible

        // mainloop: unit = (mt 0..4, nh 0..1); nh covers 6 ncols of 12 (q:0-3, k:4-7, v:8-11)
        auto run_unit = [&](int u, float (*c)[4]) {
            int mt = u >> 1, nh = u & 1;
            u32 abase = sb + AH_B + (u32)(mt * 16 + (lane & 15)) * 528u + (u32)((lane >> 4) * 16);
            u32 albase = sb + AL_B + (u32)(mt * 16 + (lane & 15)) * 272u + (u32)((lane >> 4) * 16);
            u32 bbase = sb + QS_B + (u32)(lane & 7) * 272u + (u32)(((lane >> 3) & 1) * 16)
                      + (u32)(nh * 6 * 8) * 272u;
#pragma unroll
            for (int nt = 0; nt < 6; ++nt)
#pragma unroll
                for (int e = 0; e < 4; ++e) c[nt][e] = 0.f;
#pragma unroll
            for (int k = 0; k < 8; ++k) {
                u32 ah[4], al[4];
                ldsm4(ah, abase + (u32)k * 32u);
                ldsm4(al, albase + (u32)k * 32u);
#pragma unroll
                for (int nt = 0; nt < 6; ++nt) {
                    u32 bh[2];
                    ldsm2(bh, bbase + (u32)(nt * 8) * 272u + (u32)k * 32u);
                    mma16816(c[nt], ah, bh);
                    mma16816(c[nt], al, bh);
                }
            }
        };
        auto store_unit = [&](int u, float (*c)[4]) {
            int mt = u >> 1, nh = u & 1;
            int rlo = mt * 16 + row_lo0, rhi = rlo + 8;
#pragma unroll
            for (int nt = 0; nt < 6; ++nt) {
                int ncol = nh * 6 + nt;
                float* bufp; int oc;
                if (ncol < 4)      { bufp = qsf; oc = ncol * 8 + col0; }
                else if (ncol < 8) { bufp = ksf; oc = (ncol - 4) * 8 + col0; }
                else               { bufp = vsf; oc = (ncol - 8) * 8 + col0; }
                if (rlo < 68)
                    *(float2*)(bufp + rlo * 36 + oc) = make_float2(c[nt][0], c[nt][1]);
                if (rhi < 68)
                    *(float2*)(bufp + rhi * 36 + oc) = make_float2(c[nt][2], c[nt][3]);
            }
        };

        float c0[6][4];
        run_unit(wid, c0);
        float c1[6][4];
        if (wid < 2) run_unit(wid + 8, c1);
        __syncthreads();   // ALL B-stage reads complete before qs/ks/vs overwrite the region
        store_unit(wid, c0);
        if (wid < 2) store_unit(wid + 8, c1);
        __syncthreads();   // q/k/v visible

        // ---- attention: 16 tasks = (tl 0..3, hl 0..3); lanes 0..16 = query joint n ----
        for (int t = wid; t < 16; t += 8) {
            int tl = t >> 2;
            int hl = t & 3;
            int tok = tl * 17 + lane;              // valid for lane<17
            bool act = lane < 17;
            const float* kb = ksf + (tl * 17) * 36 + hl * 8;   // warp-uniform (broadcast loads)
            const float* vb = vsf + (tl * 17) * 36 + hl * 8;
            const float* qp = qsf + tok * 36 + hl * 8;
            const float* mb = mbf + hl * 289 + lane * 17;
            float4 q0 = *(const float4*)(qp);
            float4 q1 = *(const float4*)(qp + 4);
            float ev[17];
            float mx = -3.4e38f;
#pragma unroll
            for (int m = 0; m < 17; ++m) {
                const float* kp = kb + m * 36;
                float4 k0 = *(const float4*)(kp);
                float4 k1 = *(const float4*)(kp + 4);
                float d0 = q0.x * k0.x;
                d0 = fmaf(q0.y, k0.y, d0); d0 = fmaf(q0.z, k0.z, d0); d0 = fmaf(q0.w, k0.w, d0);
                d0 = fmaf(q1.x, k1.x, d0); d0 = fmaf(q1.y, k1.y, d0);
                d0 = fmaf(q1.z, k1.z, d0); d0 = fmaf(q1.w, k1.w, d0);
                ev[m] = fmaf(d0, inv_s, mb[m]);
                mx = fmaxf(mx, ev[m]);
            }
            float s = 0.f;
#pragma unroll
            for (int m = 0; m < 17; ++m) { ev[m] = __expf(ev[m] - mx); s += ev[m]; }
            float inv = __fdividef(1.0f, s);
            float a0x = 0.f, a0y = 0.f, a0z = 0.f, a0w = 0.f;
            float a1x = 0.f, a1y = 0.f, a1z = 0.f, a1w = 0.f;
#pragma unroll
            for (int m = 0; m < 17; ++m) {
                const float* vp = vb + m * 36;
                float4 v0 = *(const float4*)(vp);
                float4 v1 = *(const float4*)(vp + 4);
                float pm = ev[m];
                a0x = fmaf(pm, v0.x, a0x); a0y = fmaf(pm, v0.y, a0y);
                a0z = fmaf(pm, v0.z, a0z); a0w = fmaf(pm, v0.w, a0w);
                a1x = fmaf(pm, v1.x, a1x); a1y = fmaf(pm, v1.y, a1y);
                a1z = fmaf(pm, v1.z, a1z); a1w = fmaf(pm, v1.w, a1w);
            }
            if (act) {
                u32 h0, h1, h2, h3;
                pack2h(a0x * inv, a0y * inv, h0);
                pack2h(a0z * inv, a0w * inv, h1);
                pack2h(a1x * inv, a1y * inv, h2);
                pack2h(a1z * inv, a1w * inv, h3);
                u32 off = (u32)tok * 528u + 256u + (u32)g * 64u + (u32)hl * 16u;
                *(uint4*)(sp + AH_B + off) = make_uint4(h0, h1, h2, h3);
            }
        }
    }

    // ---- Phase C: conv1x1 via MMA (K=256; lo only for k<8), 4 chunks of 64 outputs ----
    const float* bnsc = (const float*)(sp + BNS_B);
    const float* bnsh = (const float*)(sp + BNB_B);
    const u32 CW = QS_B;                // conv weight stage: 33792 B, spans qs/ks/vs + part of mask
    for (int cb = 0; cb < 4; ++cb) {
        __syncthreads();   // prev stage ldsm reads done; attention writes visible (cb=0)
        {
            const char* src = (const char*)&g_Bconv[cb][0];
            for (int j = tid; j < 2112; j += 256)
                cpasync16(sb + CW + (u32)j * 16u, src + (size_t)j * 16);
            asm volatile("cp.async.commit_group;" ::: "memory");
            asm volatile("cp.async.wait_group 0;" ::: "memory");
        }
        __syncthreads();   // weights visible to all

        // 10 units = (mt 0..4, nh 0..1); nh covers 4 n-tiles (32 outputs)
        for (int u = wid; u < 10; u += 8) {
            int mt = u >> 1, nh = u & 1;
            u32 abase = sb + AH_B + (u32)(mt * 16 + (lane & 15)) * 528u + (u32)((lane >> 4) * 16);
            u32 albase = sb + AL_B + (u32)(mt * 16 + (lane & 15)) * 272u + (u32)((lane >> 4) * 16);
            u32 bb0 = sb + CW + (u32)(lane & 7) * 528u + (u32)(((lane >> 3) & 1) * 16);
            float c[4][4];
#pragma unroll
            for (int nt = 0; nt < 4; ++nt)
#pragma unroll
                for (int e = 0; e < 4; ++e) c[nt][e] = 0.f;
#pragma unroll 4
            for (int k = 0; k < 16; ++k) {
                u32 ah[4];
                ldsm4(ah, abase + (u32)k * 32u);
                u32 al[4];
                if (k < 8) ldsm4(al, albase + (u32)k * 32u);
#pragma unroll
                for (int nt = 0; nt < 4; ++nt) {
                    int ncol = nh * 4 + nt;
                    u32 bh[2];
                    ldsm2(bh, bb0 + (u32)(ncol * 8) * 528u + (u32)k * 32u);
                    mma16816(c[nt], ah, bh);
                    if (k < 8) mma16816(c[nt], al, bh);
                }
            }
            // BN + ReLU + direct store
            int rlo = mt * 16 + row_lo0, rhi = rlo + 8;
#pragma unroll
            for (int nt = 0; nt < 4; ++nt) {
                int og = cb * 64 + nh * 32 + nt * 8 + col0;
                float s0 = bnsc[og], h0 = bnsh[og];
                float s1 = bnsc[og + 1], h1 = bnsh[og + 1];
                float* op0 = out + (size_t)(b * 256 + og) * 8704 + (size_t)t0 * 17;
                float* op1 = op0 + 8704;
                if (rlo < 68) {
                    op0[rlo] = fmaxf(fmaf(c[nt][0], s0, h0), 0.0f);
                    op1[rlo] = fmaxf(fmaf(c[nt][1], s1, h1), 0.0f);
                }
                if (rhi < 68) {
                    op0[rhi] = fmaxf(fmaf(c[nt][2], s0, h0), 0.0f);
                    op1[rhi] = fmaxf(fmaf(c[nt][3], s1, h1), 0.0f);
                }
            }
        }
    }
}

// ---------------- launch ----------------
extern "C" void kernel_launch(void* const* d_in, const int* in_sizes, int n_in,
                              void* d_out, int out_size) {
    const float* x      = (const float*)d_in[0];
    const float* adj    = (const float*)d_in[1];
    const float* Wq     = (const float*)d_in[2];
    const float* Wk     = (const float*)d_in[3];
    const float* Wv     = (const float*)d_in[4];
    const float* adj2   = (const float*)d_in[5];
    const float* convw  = (const float*)d_in[6];
    const float* bng    = (const float*)d_in[7];
    const float* bnb    = (const float*)d_in[8];
    const float* bnm    = (const float*)d_in[9];
    const float* bnv    = (const float*)d_in[10];
    float* out = (float*)d_out;

    cudaFuncSetAttribute(gab_kernel, cudaFuncAttributeMaxDynamicSharedMemorySize, SMEM_BYTES);

    prep_kernel<<<(4 * 96 * 128 + 256 * 256 + 255) / 256, 256>>>(Wq, Wk, Wv, convw);
    gab_kernel<<<4096, 256, SMEM_BYTES>>>(x, adj, adj2, bng, bnb, bnm, bnv, out);
}